// round 11
// baseline (speedup 1.0000x reference)
#include <cuda_runtime.h>
#include <cuda_bf16.h>
#include <cstdint>

#define BATCH 8
#define CC    64
#define DD    8
#define NPIX  4096

#define KSCALE 0.18033688011112042f

// ---------------- device scratch ----------------
__device__ float         g_Q[BATCH * NPIX * DD];
__device__ float         g_K[BATCH * NPIX * DD];
__device__ __nv_bfloat16 g_Vbf[BATCH * CC * NPIX]; // [b][c][m]
__device__ float         g_Zp[4 * BATCH * NPIX];
__device__ float         g_Rz[BATCH * NPIX];
__device__ float         g_O0[BATCH * CC];

__device__ __forceinline__ uint32_t f2tf32(float f) {
    uint32_t u; asm("cvt.rna.tf32.f32 %0, %1;" : "=r"(u) : "f"(f)); return u;
}
__device__ __forceinline__ float ex2(float x) {
    float r; asm("ex2.approx.f32 %0, %1;" : "=f"(r) : "f"(x)); return r;
}
__device__ __forceinline__ uint32_t bf2(float lo, float hi) {
    uint32_t r; asm("cvt.rn.bf16x2.f32 %0, %1, %2;" : "=r"(r) : "f"(hi), "f"(lo));
    return r;
}
__device__ __forceinline__ uint4 cvt4(float4 t) {
    uint4 u;
    u.x = f2tf32(t.x); u.y = f2tf32(t.y); u.z = f2tf32(t.z); u.w = f2tf32(t.w);
    return u;
}
__device__ __forceinline__ void mma_tf32(float* c, const uint32_t* a,
                                         uint32_t b0, uint32_t b1) {
    asm volatile(
        "mma.sync.aligned.m16n8k8.row.col.f32.tf32.tf32.f32 "
        "{%0,%1,%2,%3}, {%4,%5,%6,%7}, {%8,%9}, {%0,%1,%2,%3};"
        : "+f"(c[0]), "+f"(c[1]), "+f"(c[2]), "+f"(c[3])
        : "r"(a[0]), "r"(a[1]), "r"(a[2]), "r"(a[3]), "r"(b0), "r"(b1));
}
__device__ __forceinline__ void mma_bf16(float* c, const uint32_t* a,
                                         uint32_t b0, uint32_t b1) {
    asm volatile(
        "mma.sync.aligned.m16n8k16.row.col.f32.bf16.bf16.f32 "
        "{%0,%1,%2,%3}, {%4,%5,%6,%7}, {%8,%9}, {%0,%1,%2,%3};"
        : "+f"(c[0]), "+f"(c[1]), "+f"(c[2]), "+f"(c[3])
        : "r"(a[0]), "r"(a[1]), "r"(a[2]), "r"(a[3]), "r"(b0), "r"(b1));
}
__device__ __forceinline__ void cp_async16(uint32_t dst, const void* src) {
    asm volatile("cp.async.ca.shared.global [%0], [%1], 16;"
                 :: "r"(dst), "l"(src));
}

// ---------------- 1: projections ----------------
__global__ void __launch_bounds__(256) proj_kernel(
    const float* __restrict__ x,
    const float* __restrict__ Wq, const float* __restrict__ bq,
    const float* __restrict__ Wk, const float* __restrict__ bk,
    const float* __restrict__ Wv, const float* __restrict__ bv)
{
    __shared__ float sW[CC * 80];
    __shared__ float sB[80];
    const int tid = threadIdx.x;
    const int b = blockIdx.y;
    const int s = tid & 63;
    const int h = tid >> 6;
    const int ch0 = h * 20;

    for (int i = tid; i < CC * 80; i += 256) {
        int c = i / 80, j = i % 80;
        float w;
        if (j < 8)       w = Wq[j * CC + c];
        else if (j < 16) w = Wk[(j - 8) * CC + c] * KSCALE;
        else             w = Wv[(j - 16) * CC + c];
        sW[c * 80 + j] = w;
    }
    if (tid < 80) {
        float bb;
        if (tid < 8)       bb = bq[tid];
        else if (tid < 16) bb = bk[tid - 8] * KSCALE;
        else               bb = bv[tid - 16];
        sB[tid] = bb;
    }
    __syncthreads();

    float a[4][20];
#pragma unroll
    for (int p = 0; p < 4; p++)
#pragma unroll
        for (int j = 0; j < 20; j++) a[p][j] = 0.f;

    const int nb = blockIdx.x * 256 + s;
    const float* xb = x + ((size_t)b * CC << 12) + nb;
#pragma unroll 1
    for (int c = 0; c < CC; c += 2) {
        float x0[4], x1[4];
#pragma unroll
        for (int p = 0; p < 4; p++) {
            x0[p] = xb[((size_t)c << 12) + p * 64];
            x1[p] = xb[((size_t)(c + 1) << 12) + p * 64];
        }
        const float* w0 = sW + c * 80 + ch0;
        const float* w1 = sW + (c + 1) * 80 + ch0;
#pragma unroll
        for (int j = 0; j < 20; j++) {
            float ww0 = w0[j], ww1 = w1[j];
#pragma unroll
            for (int p = 0; p < 4; p++) {
                a[p][j] = fmaf(ww0, x0[p], a[p][j]);
                a[p][j] = fmaf(ww1, x1[p], a[p][j]);
            }
        }
    }

#pragma unroll
    for (int p = 0; p < 4; p++) {
        const int n = nb + p * 64;
        if (h == 0) {
            float4 q0 = make_float4(a[p][0] + sB[0], a[p][1] + sB[1],
                                    a[p][2] + sB[2], a[p][3] + sB[3]);
            float4 q1 = make_float4(a[p][4] + sB[4], a[p][5] + sB[5],
                                    a[p][6] + sB[6], a[p][7] + sB[7]);
            float4 k0 = make_float4(a[p][8] + sB[8], a[p][9] + sB[9],
                                    a[p][10] + sB[10], a[p][11] + sB[11]);
            float4 k1 = make_float4(a[p][12] + sB[12], a[p][13] + sB[13],
                                    a[p][14] + sB[14], a[p][15] + sB[15]);
            float4* qo = (float4*)(g_Q + ((b << 12) + n) * DD);
            qo[0] = q0; qo[1] = q1;
            float4* ko = (float4*)(g_K + ((b << 12) + n) * DD);
            ko[0] = k0; ko[1] = k1;
#pragma unroll
            for (int j = 16; j < 20; j++)
                g_Vbf[(((size_t)b * CC + (j - 16)) << 12) + n] =
                    __float2bfloat16(a[p][j] + sB[j]);
        } else {
#pragma unroll
            for (int j = 0; j < 20; j++) {
                int ch = ch0 - 16 + j;
                g_Vbf[(((size_t)b * CC + ch) << 12) + n] =
                    __float2bfloat16(a[p][j] + sB[ch0 + j]);
            }
        }
    }
}

// ---------------- 2: Zp[m] partial column sums via mma ----------------
__global__ void __launch_bounds__(256) zr_kernel()
{
    __shared__ uint32_t sK[64 * 12];
    __shared__ uint32_t sQ[128 * 12];
    __shared__ float    szp[8 * 64];

    const int tid  = threadIdx.x;
    const int lane = tid & 31;
    const int wid  = tid >> 5;
    const int g  = lane >> 2;
    const int tg = lane & 3;
    const int b = blockIdx.z;
    const int ns = blockIdx.y;
    const int m_base = blockIdx.x * 64;

    if (tid < 128) {
        float4 t = ((const float4*)(g_K + ((b << 12) + m_base) * DD))[tid];
        *(uint4*)(sK + (tid >> 1) * 12 + (tid & 1) * 4) = cvt4(t);
    }

    float zacc[16];
#pragma unroll
    for (int i = 0; i < 16; i++) zacc[i] = 0.f;

    for (int t = 0; t < 8; t++) {
        __syncthreads();
        {
            const int nb = ns * 1024 + t * 128;
            float4 tq = ((const float4*)(g_Q + ((b << 12) + nb) * DD))[tid];
            *(uint4*)(sQ + (tid >> 1) * 12 + (tid & 1) * 4) = cvt4(tq);
        }
        __syncthreads();

        const int nrow = wid * 16 + g;
        uint32_t a[4];
        a[0] = sQ[nrow * 12 + tg];
        a[1] = sQ[(nrow + 8) * 12 + tg];
        a[2] = sQ[nrow * 12 + tg + 4];
        a[3] = sQ[(nrow + 8) * 12 + tg + 4];

#pragma unroll
        for (int mt8 = 0; mt8 < 8; mt8++) {
            uint32_t b0 = sK[(mt8 * 8 + g) * 12 + tg];
            uint32_t b1 = sK[(mt8 * 8 + g) * 12 + tg + 4];
            float c[4] = {0.f, 0.f, 0.f, 0.f};
            mma_tf32(c, a, b0, b1);
            zacc[mt8 * 2 + 0] += ex2(c[0]) + ex2(c[2]);
            zacc[mt8 * 2 + 1] += ex2(c[1]) + ex2(c[3]);
        }
    }

#pragma unroll
    for (int i = 0; i < 16; i++) {
        zacc[i] += __shfl_xor_sync(0xffffffffu, zacc[i], 4);
        zacc[i] += __shfl_xor_sync(0xffffffffu, zacc[i], 8);
        zacc[i] += __shfl_xor_sync(0xffffffffu, zacc[i], 16);
    }
    if (lane < 4) {
#pragma unroll
        for (int i = 0; i < 16; i++)
            szp[wid * 64 + (i >> 1) * 8 + lane * 2 + (i & 1)] = zacc[i];
    }
    __syncthreads();
    if (tid < 64) {
        float z = 0.f;
#pragma unroll
        for (int w = 0; w < 8; w++) z += szp[w * 64 + tid];
        g_Zp[(ns * BATCH + b) * NPIX + m_base + tid] = z;
    }
}

// ---------------- 2b: fused Rz + y + O0 ----------------
// grid (B), 256 threads.
__global__ void __launch_bounds__(256) o0_kernel(
    const float* __restrict__ x,
    const float* __restrict__ Wv, const float* __restrict__ bv)
{
    __shared__ float s_rz[NPIX];    // 16 KB
    __shared__ float s_y[CC];
    __shared__ float s_red[8];
    const int b = blockIdx.x, tid = threadIdx.x;
    const int lane = tid & 31, wid = tid >> 5;

    // Rz from Zp partials; write global + smem
    for (int i = tid; i < NPIX; i += 256) {
        float z = g_Zp[(0 * BATCH + b) * NPIX + i]
                + g_Zp[(1 * BATCH + b) * NPIX + i]
                + g_Zp[(2 * BATCH + b) * NPIX + i]
                + g_Zp[(3 * BATCH + b) * NPIX + i];
        float r = 1.0f / z;
        g_Rz[(b << 12) + i] = r;
        s_rz[i] = r;
    }
    __syncthreads();

    // y[c] = sum_m x[b][c][m] * rz[m]; warp wid owns c in [wid*8, wid*8+8)
    {
        float acc[8];
#pragma unroll
        for (int j = 0; j < 8; j++) acc[j] = 0.f;
        const float4* xb = (const float4*)(x + (((size_t)b * CC + wid * 8) << 12));
        const float4* rzv = (const float4*)s_rz;
        for (int i = lane; i < 1024; i += 32) {
            float4 rv = rzv[i];
#pragma unroll
            for (int j = 0; j < 8; j++) {
                float4 xv = xb[j * 1024 + i];
                acc[j] += xv.x * rv.x + xv.y * rv.y + xv.z * rv.z + xv.w * rv.w;
            }
        }
#pragma unroll
        for (int j = 0; j < 8; j++) {
#pragma unroll
            for (int o = 16; o; o >>= 1)
                acc[j] += __shfl_xor_sync(0xffffffffu, acc[j], o);
        }
        if (lane == 0) {
#pragma unroll
            for (int j = 0; j < 8; j++) s_y[wid * 8 + j] = acc[j];
        }
    }
    // S = sum rz
    {
        float s = 0.f;
        for (int i = tid; i < NPIX; i += 256) s += s_rz[i];
#pragma unroll
        for (int o = 16; o; o >>= 1)
            s += __shfl_xor_sync(0xffffffffu, s, o);
        if (lane == 0) s_red[wid] = s;
    }
    __syncthreads();

    if (tid < CC) {
        float S = 0.f;
#pragma unroll
        for (int w = 0; w < 8; w++) S += s_red[w];
        float acc = bv[tid] * S;
#pragma unroll 8
        for (int c = 0; c < CC; c++)
            acc = fmaf(Wv[tid * CC + c], s_y[c], acc);
        g_O0[b * CC + tid] = acc;
    }
}

// ---------------- 3: term2 out2, low-register warp tiling ----------------
// smem u32: sPbf[128*36]=4608 | sVb0 4608.. | sVb1 | sQ | sK | sRz
#define OFF_PBF 0                       // [128][36]
#define OFF_VB0 4608                    // [64][36]
#define OFF_VB1 6912
#define OFF_Q   9216                    // [128][12]
#define OFF_K   10752                   // [64][12]
#define OFF_RZ  11520                   // [64]
#define OUT_SMEM ((11520 + 64) * 4)     // 46336 B

__global__ void __launch_bounds__(256, 2) out_kernel(float* __restrict__ out)
{
    extern __shared__ uint32_t sm[];
    uint32_t* sPbf = sm + OFF_PBF;
    uint32_t* sQ   = sm + OFF_Q;
    uint32_t* sK   = sm + OFF_K;
    float*    sRz  = (float*)(sm + OFF_RZ);

    const int tid  = threadIdx.x;
    const int lane = tid & 31;
    const int wid  = tid >> 5;
    const int b    = blockIdx.y;
    const int n_base = blockIdx.x * 128;
    const int g  = lane >> 2;
    const int tg = lane & 3;

    const int ws    = wid * 16;         // phase-A n rows
    const int Mwoff = (wid & 3) * 32;   // phase-B n offset
    const int Nwoff = (wid >> 2) * 32;  // phase-B c offset

    // Q tile once
    {
        const float4* qg = (const float4*)(g_Q + ((b << 12) + n_base) * DD);
        float4 t = qg[tid];
        *(uint4*)(sQ + (tid >> 1) * 12 + (tid & 1) * 4) = cvt4(t);
    }
    float4 vK = make_float4(0.f, 0.f, 0.f, 0.f);
    float vRz = 0.f;
    if (tid < 128) vK = ((const float4*)(g_K + (b << 12) * DD))[tid];
    if (tid < 64)  vRz = g_Rz[(b << 12) + tid];
    {   // cp.async V(0) -> buf0
        const char* src = (const char*)(g_Vbf + ((size_t)b * CC << 12));
#pragma unroll
        for (int k = 0; k < 2; k++) {
            int q = tid + k * 256;
            int row = q >> 3, off = (q & 7) * 16;
            uint32_t dst = (uint32_t)__cvta_generic_to_shared(
                (char*)(sm + OFF_VB0) + row * 144 + off);
            cp_async16(dst, src + ((size_t)row << 13) + off);
        }
        asm volatile("cp.async.commit_group;");
    }
    __syncthreads();

    uint32_t aq[4];
    aq[0] = sQ[(ws + g) * 12 + tg];
    aq[1] = sQ[(ws + g + 8) * 12 + tg];
    aq[2] = sQ[(ws + g) * 12 + tg + 4];
    aq[3] = sQ[(ws + g + 8) * 12 + tg + 4];

    float acc[32];
#pragma unroll
    for (int i = 0; i < 32; i++) acc[i] = 0.f;

    for (int mt = 0; mt < 64; mt++) {
        const int par = mt & 1;
        __syncthreads();                        // S1: prev phase B done

        // store prefetched K(t)/rz(t)
        if (tid < 128)
            *(uint4*)(sK + (tid >> 1) * 12 + (tid & 1) * 4) = cvt4(vK);
        if (tid < 64) sRz[tid] = vRz;

        // reg-prefetch K(t+1)/rz(t+1)
        if (mt < 63) {
            const int mb2 = (mt + 1) * 64;
            if (tid < 128)
                vK = ((const float4*)(g_K + ((b << 12) + mb2) * DD))[tid];
            if (tid < 64) vRz = g_Rz[(b << 12) + mb2 + tid];
        }
        asm volatile("cp.async.wait_group 0;"); // V(t) arrived
        __syncthreads();                        // S2

        // phase A: QK mma -> delta' -> bf16 pairs
#pragma unroll
        for (int mt8 = 0; mt8 < 8; mt8++) {
            uint32_t b0 = sK[(mt8 * 8 + g) * 12 + tg];
            uint32_t b1 = sK[(mt8 * 8 + g) * 12 + tg + 4];
            float c[4] = {0.f, 0.f, 0.f, 0.f};
            mma_tf32(c, aq, b0, b1);
            float2 rr = *(const float2*)(sRz + mt8 * 8 + tg * 2);
            float d0 = fmaf(ex2(c[0]), rr.x, -rr.x);
            float d1 = fmaf(ex2(c[1]), rr.y, -rr.y);
            float d2 = fmaf(ex2(c[2]), rr.x, -rr.x);
            float d3 = fmaf(ex2(c[3]), rr.y, -rr.y);
            sPbf[(ws + g) * 36 + mt8 * 4 + tg]     = bf2(d0, d1);
            sPbf[(ws + g + 8) * 36 + mt8 * 4 + tg] = bf2(d2, d3);
        }

        // cp.async V(t+1) into other buffer
        if (mt < 63) {
            const char* src = (const char*)(g_Vbf + ((size_t)b * CC << 12))
                            + (mt + 1) * 128;
            char* dbuf = (char*)(sm + (par ? OFF_VB0 : OFF_VB1));
#pragma unroll
            for (int k = 0; k < 2; k++) {
                int q = tid + k * 256;
                int row = q >> 3, off = (q & 7) * 16;
                uint32_t dst = (uint32_t)__cvta_generic_to_shared(
                    dbuf + row * 144 + off);
                cp_async16(dst, src + ((size_t)row << 13) + off);
            }
            asm volatile("cp.async.commit_group;");
        }
        __syncthreads();                        // S3: P(t) visible

        // phase B: warp covers n 32 x c 32 x m 64 (full), acc[32]
        const uint32_t* sVb = sm + (par ? OFF_VB1 : OFF_VB0);
#pragma unroll
        for (int ks = 0; ks < 4; ks++) {
            const int colb = ks * 8 + tg;
            uint32_t a[2][4];
#pragma unroll
            for (int mf = 0; mf < 2; mf++) {
                const uint32_t* ap = sPbf + (Mwoff + mf * 16 + g) * 36 + colb;
                a[mf][0] = ap[0];
                a[mf][1] = ap[8 * 36];
                a[mf][2] = ap[4];
                a[mf][3] = ap[8 * 36 + 4];
            }
#pragma unroll
            for (int nf = 0; nf < 4; nf++) {
                const uint32_t* bp = sVb + (Nwoff + nf * 8 + g) * 36 + colb;
                uint32_t b0 = bp[0], b1 = bp[4];
                mma_bf16(acc + (0 * 4 + nf) * 4, a[0], b0, b1);
                mma_bf16(acc + (1 * 4 + nf) * 4, a[1], b0, b1);
            }
        }
    }

    // epilogue: direct store + O0 (no cross-warp reduction)
#pragma unroll
    for (int mf = 0; mf < 2; mf++)
#pragma unroll
        for (int nf = 0; nf < 4; nf++) {
            int n = n_base + Mwoff + mf * 16 + g;
            int c = Nwoff + nf * 8 + tg * 2;
            float o0a_ = __ldg(g_O0 + b * CC + c);
            float o0b_ = __ldg(g_O0 + b * CC + c + 1);
            float* o = out + (((size_t)b * CC + c) << 12) + n;
            const float* ac = acc + (mf * 4 + nf) * 4;
            o[0]        = ac[0] + o0a_;
            o[4096]     = ac[1] + o0b_;
            o[8]        = ac[2] + o0a_;
            o[4096 + 8] = ac[3] + o0b_;
        }
}

// ---------------- launch ----------------
extern "C" void kernel_launch(void* const* d_in, const int* in_sizes, int n_in,
                              void* d_out, int out_size)
{
    const float* x  = (const float*)d_in[0];
    const float* Wq = (const float*)d_in[1];
    const float* bq = (const float*)d_in[2];
    const float* Wk = (const float*)d_in[3];
    const float* bk = (const float*)d_in[4];
    const float* Wv = (const float*)d_in[5];
    const float* bv = (const float*)d_in[6];
    float* out = (float*)d_out;

    cudaFuncSetAttribute(out_kernel, cudaFuncAttributeMaxDynamicSharedMemorySize, OUT_SMEM);

    proj_kernel<<<dim3(16, BATCH), 256>>>(x, Wq, bq, Wk, bk, Wv, bv);
    zr_kernel<<<dim3(64, 4, BATCH), 256>>>();
    o0_kernel<<<BATCH, 256>>>(x, Wv, bv);
    out_kernel<<<dim3(32, BATCH), 256, OUT_SMEM>>>(out);
}

// round 12
// speedup vs baseline: 1.0693x; 1.0693x over previous
#include <cuda_runtime.h>
#include <cuda_bf16.h>
#include <cstdint>

#define BATCH 8
#define CC    64
#define DD    8
#define NPIX  4096

#define KSCALE 0.18033688011112042f

// ---------------- device scratch ----------------
__device__ float         g_Q[BATCH * NPIX * DD];
__device__ float         g_K[BATCH * NPIX * DD];
__device__ __nv_bfloat16 g_Vbf[BATCH * CC * NPIX]; // [b][c][m]
__device__ float         g_Zp[4 * BATCH * NPIX];
__device__ float         g_Rz[BATCH * NPIX];
__device__ float         g_Sp[128];                // per-rza-block sum(rz)
__device__ float         g_y[BATCH * CC];
__device__ float         g_O0[BATCH * CC];

__device__ __forceinline__ uint32_t f2tf32(float f) {
    uint32_t u; asm("cvt.rna.tf32.f32 %0, %1;" : "=r"(u) : "f"(f)); return u;
}
__device__ __forceinline__ float ex2(float x) {
    float r; asm("ex2.approx.f32 %0, %1;" : "=f"(r) : "f"(x)); return r;
}
__device__ __forceinline__ uint32_t bf2(float lo, float hi) {
    uint32_t r; asm("cvt.rn.bf16x2.f32 %0, %1, %2;" : "=r"(r) : "f"(hi), "f"(lo));
    return r;
}
__device__ __forceinline__ uint4 cvt4(float4 t) {
    uint4 u;
    u.x = f2tf32(t.x); u.y = f2tf32(t.y); u.z = f2tf32(t.z); u.w = f2tf32(t.w);
    return u;
}
__device__ __forceinline__ void mma_tf32(float* c, const uint32_t* a,
                                         uint32_t b0, uint32_t b1) {
    asm volatile(
        "mma.sync.aligned.m16n8k8.row.col.f32.tf32.tf32.f32 "
        "{%0,%1,%2,%3}, {%4,%5,%6,%7}, {%8,%9}, {%0,%1,%2,%3};"
        : "+f"(c[0]), "+f"(c[1]), "+f"(c[2]), "+f"(c[3])
        : "r"(a[0]), "r"(a[1]), "r"(a[2]), "r"(a[3]), "r"(b0), "r"(b1));
}
__device__ __forceinline__ void mma_bf16(float* c, const uint32_t* a,
                                         uint32_t b0, uint32_t b1) {
    asm volatile(
        "mma.sync.aligned.m16n8k16.row.col.f32.bf16.bf16.f32 "
        "{%0,%1,%2,%3}, {%4,%5,%6,%7}, {%8,%9}, {%0,%1,%2,%3};"
        : "+f"(c[0]), "+f"(c[1]), "+f"(c[2]), "+f"(c[3])
        : "r"(a[0]), "r"(a[1]), "r"(a[2]), "r"(a[3]), "r"(b0), "r"(b1));
}
__device__ __forceinline__ void cp_async16(uint32_t dst, const void* src) {
    asm volatile("cp.async.ca.shared.global [%0], [%1], 16;"
                 :: "r"(dst), "l"(src));
}

// ---------------- 1: projections ----------------
__global__ void __launch_bounds__(256) proj_kernel(
    const float* __restrict__ x,
    const float* __restrict__ Wq, const float* __restrict__ bq,
    const float* __restrict__ Wk, const float* __restrict__ bk,
    const float* __restrict__ Wv, const float* __restrict__ bv)
{
    __shared__ float sW[CC * 80];
    __shared__ float sB[80];
    const int tid = threadIdx.x;
    const int b = blockIdx.y;
    const int s = tid & 63;
    const int h = tid >> 6;
    const int ch0 = h * 20;

    for (int i = tid; i < CC * 80; i += 256) {
        int c = i / 80, j = i % 80;
        float w;
        if (j < 8)       w = Wq[j * CC + c];
        else if (j < 16) w = Wk[(j - 8) * CC + c] * KSCALE;
        else             w = Wv[(j - 16) * CC + c];
        sW[c * 80 + j] = w;
    }
    if (tid < 80) {
        float bb;
        if (tid < 8)       bb = bq[tid];
        else if (tid < 16) bb = bk[tid - 8] * KSCALE;
        else               bb = bv[tid - 16];
        sB[tid] = bb;
    }
    __syncthreads();

    float a[4][20];
#pragma unroll
    for (int p = 0; p < 4; p++)
#pragma unroll
        for (int j = 0; j < 20; j++) a[p][j] = 0.f;

    const int nb = blockIdx.x * 256 + s;
    const float* xb = x + ((size_t)b * CC << 12) + nb;
#pragma unroll 1
    for (int c = 0; c < CC; c += 2) {
        float x0[4], x1[4];
#pragma unroll
        for (int p = 0; p < 4; p++) {
            x0[p] = xb[((size_t)c << 12) + p * 64];
            x1[p] = xb[((size_t)(c + 1) << 12) + p * 64];
        }
        const float* w0 = sW + c * 80 + ch0;
        const float* w1 = sW + (c + 1) * 80 + ch0;
#pragma unroll
        for (int j = 0; j < 20; j++) {
            float ww0 = w0[j], ww1 = w1[j];
#pragma unroll
            for (int p = 0; p < 4; p++) {
                a[p][j] = fmaf(ww0, x0[p], a[p][j]);
                a[p][j] = fmaf(ww1, x1[p], a[p][j]);
            }
        }
    }

#pragma unroll
    for (int p = 0; p < 4; p++) {
        const int n = nb + p * 64;
        if (h == 0) {
            float4 q0 = make_float4(a[p][0] + sB[0], a[p][1] + sB[1],
                                    a[p][2] + sB[2], a[p][3] + sB[3]);
            float4 q1 = make_float4(a[p][4] + sB[4], a[p][5] + sB[5],
                                    a[p][6] + sB[6], a[p][7] + sB[7]);
            float4 k0 = make_float4(a[p][8] + sB[8], a[p][9] + sB[9],
                                    a[p][10] + sB[10], a[p][11] + sB[11]);
            float4 k1 = make_float4(a[p][12] + sB[12], a[p][13] + sB[13],
                                    a[p][14] + sB[14], a[p][15] + sB[15]);
            float4* qo = (float4*)(g_Q + ((b << 12) + n) * DD);
            qo[0] = q0; qo[1] = q1;
            float4* ko = (float4*)(g_K + ((b << 12) + n) * DD);
            ko[0] = k0; ko[1] = k1;
#pragma unroll
            for (int j = 16; j < 20; j++)
                g_Vbf[(((size_t)b * CC + (j - 16)) << 12) + n] =
                    __float2bfloat16(a[p][j] + sB[j]);
        } else {
#pragma unroll
            for (int j = 0; j < 20; j++) {
                int ch = ch0 - 16 + j;
                g_Vbf[(((size_t)b * CC + ch) << 12) + n] =
                    __float2bfloat16(a[p][j] + sB[ch0 + j]);
            }
        }
    }
}

// ---------------- 2: Zp[m] partial column sums via mma ----------------
__global__ void __launch_bounds__(256) zr_kernel()
{
    __shared__ uint32_t sK[64 * 12];
    __shared__ uint32_t sQ[128 * 12];
    __shared__ float    szp[8 * 64];

    const int tid  = threadIdx.x;
    const int lane = tid & 31;
    const int wid  = tid >> 5;
    const int g  = lane >> 2;
    const int tg = lane & 3;
    const int b = blockIdx.z;
    const int ns = blockIdx.y;
    const int m_base = blockIdx.x * 64;

    if (tid < 128) {
        float4 t = ((const float4*)(g_K + ((b << 12) + m_base) * DD))[tid];
        *(uint4*)(sK + (tid >> 1) * 12 + (tid & 1) * 4) = cvt4(t);
    }

    float zacc[16];
#pragma unroll
    for (int i = 0; i < 16; i++) zacc[i] = 0.f;

    for (int t = 0; t < 8; t++) {
        __syncthreads();
        {
            const int nb = ns * 1024 + t * 128;
            float4 tq = ((const float4*)(g_Q + ((b << 12) + nb) * DD))[tid];
            *(uint4*)(sQ + (tid >> 1) * 12 + (tid & 1) * 4) = cvt4(tq);
        }
        __syncthreads();

        const int nrow = wid * 16 + g;
        uint32_t a[4];
        a[0] = sQ[nrow * 12 + tg];
        a[1] = sQ[(nrow + 8) * 12 + tg];
        a[2] = sQ[nrow * 12 + tg + 4];
        a[3] = sQ[(nrow + 8) * 12 + tg + 4];

#pragma unroll
        for (int mt8 = 0; mt8 < 8; mt8++) {
            uint32_t b0 = sK[(mt8 * 8 + g) * 12 + tg];
            uint32_t b1 = sK[(mt8 * 8 + g) * 12 + tg + 4];
            float c[4] = {0.f, 0.f, 0.f, 0.f};
            mma_tf32(c, a, b0, b1);
            zacc[mt8 * 2 + 0] += ex2(c[0]) + ex2(c[2]);
            zacc[mt8 * 2 + 1] += ex2(c[1]) + ex2(c[3]);
        }
    }

#pragma unroll
    for (int i = 0; i < 16; i++) {
        zacc[i] += __shfl_xor_sync(0xffffffffu, zacc[i], 4);
        zacc[i] += __shfl_xor_sync(0xffffffffu, zacc[i], 8);
        zacc[i] += __shfl_xor_sync(0xffffffffu, zacc[i], 16);
    }
    if (lane < 4) {
#pragma unroll
        for (int i = 0; i < 16; i++)
            szp[wid * 64 + (i >> 1) * 8 + lane * 2 + (i & 1)] = zacc[i];
    }
    __syncthreads();
    if (tid < 64) {
        float z = 0.f;
#pragma unroll
        for (int w = 0; w < 8; w++) z += szp[w * 64 + tid];
        g_Zp[(ns * BATCH + b) * NPIX + m_base + tid] = z;
    }
}

// ---------------- 2b: Rz = 1/sum(Zp), plus S partials ----------------
__global__ void __launch_bounds__(256) rza_kernel()
{
    __shared__ float red[256];
    int i = blockIdx.x * 256 + threadIdx.x;   // 32768; 16 blocks per batch
    int b = i >> 12, m = i & 4095;
    float z = g_Zp[(0 * BATCH + b) * NPIX + m]
            + g_Zp[(1 * BATCH + b) * NPIX + m]
            + g_Zp[(2 * BATCH + b) * NPIX + m]
            + g_Zp[(3 * BATCH + b) * NPIX + m];
    float r = 1.0f / z;
    g_Rz[i] = r;
    red[threadIdx.x] = r;
    __syncthreads();
    for (int s = 128; s; s >>= 1) {
        if (threadIdx.x < s) red[threadIdx.x] += red[threadIdx.x + s];
        __syncthreads();
    }
    if (threadIdx.x == 0) g_Sp[blockIdx.x] = red[0];
}

// ---------------- 2c: y[b][c] = sum_m x[b][c][m] * rz[b][m] ----------------
__global__ void __launch_bounds__(256) o0a_kernel(const float* __restrict__ x)
{
    __shared__ float red[256];
    const int c = blockIdx.x, b = blockIdx.y, tid = threadIdx.x;
    const float4* xp = (const float4*)(x + (((size_t)b * CC + c) << 12));
    const float4* rz = (const float4*)(g_Rz + (b << 12));
    float acc = 0.f;
#pragma unroll
    for (int it = 0; it < 4; it++) {
        int m = it * 256 + tid;
        float4 xv = xp[m], rv = rz[m];
        acc = fmaf(xv.x, rv.x, acc);
        acc = fmaf(xv.y, rv.y, acc);
        acc = fmaf(xv.z, rv.z, acc);
        acc = fmaf(xv.w, rv.w, acc);
    }
    red[tid] = acc;
    __syncthreads();
    for (int s = 128; s; s >>= 1) {
        if (tid < s) red[tid] += red[tid + s];
        __syncthreads();
    }
    if (tid == 0) g_y[b * CC + c] = red[0];
}

// ---------------- 2d: O0[b][d] = Wv.y + bv*S ----------------
__global__ void __launch_bounds__(64) o0b_kernel(
    const float* __restrict__ Wv, const float* __restrict__ bv)
{
    __shared__ float sy[64];
    const int b = blockIdx.x, tid = threadIdx.x;
    sy[tid] = g_y[b * CC + tid];
    float S = 0.f;
#pragma unroll
    for (int k = 0; k < 16; k++) S += g_Sp[b * 16 + k];
    __syncthreads();
    float acc = bv[tid] * S;
#pragma unroll 8
    for (int c = 0; c < CC; c++)
        acc = fmaf(Wv[tid * CC + c], sy[c], acc);
    g_O0[b * CC + tid] = acc;
}

// ---------------- 3: term2, 128-thread blocks, single wave ----------------
// smem u32: sPbf[64][36] | sVb0[64][36] | sVb1 | sQ[64][12] | sK[64][12] | sRz[64]
#define OFF_PBF 0
#define OFF_VB0 2304
#define OFF_VB1 4608
#define OFF_Q   6912
#define OFF_K   7680
#define OFF_RZ  8448
#define OUT_SMEM ((8448 + 64) * 4)   // 34048 B

__global__ void __launch_bounds__(128, 4) out_kernel(float* __restrict__ out)
{
    extern __shared__ uint32_t sm[];
    uint32_t* sPbf = sm + OFF_PBF;
    uint32_t* sQ   = sm + OFF_Q;
    uint32_t* sK   = sm + OFF_K;
    float*    sRz  = (float*)(sm + OFF_RZ);

    const int tid  = threadIdx.x;
    const int lane = tid & 31;
    const int wid  = tid >> 5;
    const int b    = blockIdx.y;
    const int n_base = blockIdx.x * 64;
    const int g  = lane >> 2;
    const int tg = lane & 3;

    const int ws    = wid * 16;         // phase-A n rows (4 warps x 16 = 64)
    const int Mwoff = (wid & 1) * 32;   // phase-B n offset
    const int Nwoff = (wid >> 1) * 32;  // phase-B c offset

    // Q tile once: 64 rows = 128 float4
    {
        const float4* qg = (const float4*)(g_Q + ((b << 12) + n_base) * DD);
        float4 t = qg[tid];
        *(uint4*)(sQ + (tid >> 1) * 12 + (tid & 1) * 4) = cvt4(t);
    }
    float4 vK = ((const float4*)(g_K + (b << 12) * DD))[tid];
    float vRz = 0.f;
    if (tid < 64) vRz = g_Rz[(b << 12) + tid];
    {   // cp.async V(0) -> buf0: 512 chunks of 16B, 128 threads x 4
        const char* src = (const char*)(g_Vbf + ((size_t)b * CC << 12));
#pragma unroll
        for (int k = 0; k < 4; k++) {
            int q = tid + k * 128;
            int row = q >> 3, off = (q & 7) * 16;
            uint32_t dst = (uint32_t)__cvta_generic_to_shared(
                (char*)(sm + OFF_VB0) + row * 144 + off);
            cp_async16(dst, src + ((size_t)row << 13) + off);
        }
        asm volatile("cp.async.commit_group;");
    }
    __syncthreads();

    uint32_t aq[4];
    aq[0] = sQ[(ws + g) * 12 + tg];
    aq[1] = sQ[(ws + g + 8) * 12 + tg];
    aq[2] = sQ[(ws + g) * 12 + tg + 4];
    aq[3] = sQ[(ws + g + 8) * 12 + tg + 4];

    float acc[32];
#pragma unroll
    for (int i = 0; i < 32; i++) acc[i] = 0.f;

    for (int mt = 0; mt < 64; mt++) {
        const int par = mt & 1;
        __syncthreads();                        // S1: prev phase B done

        // store prefetched K(t)/rz(t)
        *(uint4*)(sK + (tid >> 1) * 12 + (tid & 1) * 4) = cvt4(vK);
        if (tid < 64) sRz[tid] = vRz;

        // reg-prefetch K(t+1)/rz(t+1)
        if (mt < 63) {
            const int mb2 = (mt + 1) * 64;
            vK = ((const float4*)(g_K + ((b << 12) + mb2) * DD))[tid];
            if (tid < 64) vRz = g_Rz[(b << 12) + mb2 + tid];
        }
        asm volatile("cp.async.wait_group 0;"); // V(t) arrived
        __syncthreads();                        // S2

        // phase A: QK mma -> delta' -> bf16 pairs (64 n x 64 m)
#pragma unroll
        for (int mt8 = 0; mt8 < 8; mt8++) {
            uint32_t b0 = sK[(mt8 * 8 + g) * 12 + tg];
            uint32_t b1 = sK[(mt8 * 8 + g) * 12 + tg + 4];
            float c[4] = {0.f, 0.f, 0.f, 0.f};
            mma_tf32(c, aq, b0, b1);
            float2 rr = *(const float2*)(sRz + mt8 * 8 + tg * 2);
            float d0 = fmaf(ex2(c[0]), rr.x, -rr.x);
            float d1 = fmaf(ex2(c[1]), rr.y, -rr.y);
            float d2 = fmaf(ex2(c[2]), rr.x, -rr.x);
            float d3 = fmaf(ex2(c[3]), rr.y, -rr.y);
            sPbf[(ws + g) * 36 + mt8 * 4 + tg]     = bf2(d0, d1);
            sPbf[(ws + g + 8) * 36 + mt8 * 4 + tg] = bf2(d2, d3);
        }

        // cp.async V(t+1) into other buffer
        if (mt < 63) {
            const char* src = (const char*)(g_Vbf + ((size_t)b * CC << 12))
                            + (mt + 1) * 128;
            char* dbuf = (char*)(sm + (par ? OFF_VB0 : OFF_VB1));
#pragma unroll
            for (int k = 0; k < 4; k++) {
                int q = tid + k * 128;
                int row = q >> 3, off = (q & 7) * 16;
                uint32_t dst = (uint32_t)__cvta_generic_to_shared(
                    dbuf + row * 144 + off);
                cp_async16(dst, src + ((size_t)row << 13) + off);
            }
            asm volatile("cp.async.commit_group;");
        }
        __syncthreads();                        // S3: P(t) visible

        // phase B: warp covers n 32 x c 32 x m 64
        const uint32_t* sVb = sm + (par ? OFF_VB1 : OFF_VB0);
#pragma unroll
        for (int ks = 0; ks < 4; ks++) {
            const int colb = ks * 8 + tg;
            uint32_t a[2][4];
#pragma unroll
            for (int mf = 0; mf < 2; mf++) {
                const uint32_t* ap = sPbf + (Mwoff + mf * 16 + g) * 36 + colb;
                a[mf][0] = ap[0];
                a[mf][1] = ap[8 * 36];
                a[mf][2] = ap[4];
                a[mf][3] = ap[8 * 36 + 4];
            }
#pragma unroll
            for (int nf = 0; nf < 4; nf++) {
                const uint32_t* bp = sVb + (Nwoff + nf * 8 + g) * 36 + colb;
                uint32_t b0 = bp[0], b1 = bp[4];
                mma_bf16(acc + (0 * 4 + nf) * 4, a[0], b0, b1);
                mma_bf16(acc + (1 * 4 + nf) * 4, a[1], b0, b1);
            }
        }
    }

    // epilogue: direct store + O0
#pragma unroll
    for (int mf = 0; mf < 2; mf++)
#pragma unroll
        for (int nf = 0; nf < 4; nf++) {
            int n = n_base + Mwoff + mf * 16 + g;
            int c = Nwoff + nf * 8 + tg * 2;
            float o0a_ = __ldg(g_O0 + b * CC + c);
            float o0b_ = __ldg(g_O0 + b * CC + c + 1);
            float* o = out + (((size_t)b * CC + c) << 12) + n;
            const float* ac = acc + (mf * 4 + nf) * 4;
            o[0]        = ac[0] + o0a_;
            o[4096]     = ac[1] + o0b_;
            o[8]        = ac[2] + o0a_;
            o[4096 + 8] = ac[3] + o0b_;
        }
}

// ---------------- launch ----------------
extern "C" void kernel_launch(void* const* d_in, const int* in_sizes, int n_in,
                              void* d_out, int out_size)
{
    const float* x  = (const float*)d_in[0];
    const float* Wq = (const float*)d_in[1];
    const float* bq = (const float*)d_in[2];
    const float* Wk = (const float*)d_in[3];
    const float* bk = (const float*)d_in[4];
    const float* Wv = (const float*)d_in[5];
    const float* bv = (const float*)d_in[6];
    float* out = (float*)d_out;

    cudaFuncSetAttribute(out_kernel, cudaFuncAttributeMaxDynamicSharedMemorySize, OUT_SMEM);

    proj_kernel<<<dim3(16, BATCH), 256>>>(x, Wq, bq, Wk, bk, Wv, bv);
    zr_kernel<<<dim3(64, 4, BATCH), 256>>>();
    rza_kernel<<<128, 256>>>();
    o0a_kernel<<<dim3(CC, BATCH), 256>>>(x);
    o0b_kernel<<<BATCH, 64>>>(Wv, bv);
    out_kernel<<<dim3(64, BATCH), 128, OUT_SMEM>>>(out);
}

// round 13
// speedup vs baseline: 1.0919x; 1.0212x over previous
#include <cuda_runtime.h>
#include <cuda_bf16.h>
#include <cstdint>

#define BATCH 8
#define CC    64
#define DD    8
#define NPIX  4096

#define KSCALE 0.18033688011112042f

// ---------------- device scratch ----------------
__device__ float         g_Q[BATCH * NPIX * DD];
__device__ float         g_K[BATCH * NPIX * DD];
__device__ __nv_bfloat16 g_Vbf[BATCH * CC * NPIX]; // [b][c][m]
__device__ float         g_Zp[4 * BATCH * NPIX];
__device__ float         g_Rz[BATCH * NPIX];
__device__ float         g_Sp[128];
__device__ float         g_y[BATCH * CC];
__device__ float         g_O0[BATCH * CC];

__device__ __forceinline__ uint32_t f2tf32(float f) {
    uint32_t u; asm("cvt.rna.tf32.f32 %0, %1;" : "=r"(u) : "f"(f)); return u;
}
__device__ __forceinline__ float ex2(float x) {
    float r; asm("ex2.approx.f32 %0, %1;" : "=f"(r) : "f"(x)); return r;
}
__device__ __forceinline__ uint32_t bf2(float lo, float hi) {
    uint32_t r; asm("cvt.rn.bf16x2.f32 %0, %1, %2;" : "=r"(r) : "f"(hi), "f"(lo));
    return r;
}
__device__ __forceinline__ uint4 cvt4(float4 t) {
    uint4 u;
    u.x = f2tf32(t.x); u.y = f2tf32(t.y); u.z = f2tf32(t.z); u.w = f2tf32(t.w);
    return u;
}
__device__ __forceinline__ void mma_tf32(float* c, const uint32_t* a,
                                         uint32_t b0, uint32_t b1) {
    asm volatile(
        "mma.sync.aligned.m16n8k8.row.col.f32.tf32.tf32.f32 "
        "{%0,%1,%2,%3}, {%4,%5,%6,%7}, {%8,%9}, {%0,%1,%2,%3};"
        : "+f"(c[0]), "+f"(c[1]), "+f"(c[2]), "+f"(c[3])
        : "r"(a[0]), "r"(a[1]), "r"(a[2]), "r"(a[3]), "r"(b0), "r"(b1));
}
__device__ __forceinline__ void mma_bf16(float* c, const uint32_t* a,
                                         uint32_t b0, uint32_t b1) {
    asm volatile(
        "mma.sync.aligned.m16n8k16.row.col.f32.bf16.bf16.f32 "
        "{%0,%1,%2,%3}, {%4,%5,%6,%7}, {%8,%9}, {%0,%1,%2,%3};"
        : "+f"(c[0]), "+f"(c[1]), "+f"(c[2]), "+f"(c[3])
        : "r"(a[0]), "r"(a[1]), "r"(a[2]), "r"(a[3]), "r"(b0), "r"(b1));
}
__device__ __forceinline__ void cp_async16(uint32_t dst, const void* src) {
    asm volatile("cp.async.ca.shared.global [%0], [%1], 16;"
                 :: "r"(dst), "l"(src));
}
__device__ __forceinline__ void ldsm4(uint32_t* r, uint32_t a) {
    asm volatile("ldmatrix.sync.aligned.m8n8.x4.shared.b16 {%0,%1,%2,%3}, [%4];"
                 : "=r"(r[0]), "=r"(r[1]), "=r"(r[2]), "=r"(r[3]) : "r"(a) : "memory");
}
__device__ __forceinline__ void ldsm2(uint32_t& r0, uint32_t& r1, uint32_t a) {
    asm volatile("ldmatrix.sync.aligned.m8n8.x2.shared.b16 {%0,%1}, [%2];"
                 : "=r"(r0), "=r"(r1) : "r"(a) : "memory");
}
__device__ __forceinline__ void stsm2(uint32_t a, uint32_t r0, uint32_t r1) {
    asm volatile("stmatrix.sync.aligned.m8n8.x2.shared.b16 [%0], {%1,%2};"
                 :: "r"(a), "r"(r0), "r"(r1) : "memory");
}

// ---------------- 1: projections ----------------
__global__ void __launch_bounds__(256) proj_kernel(
    const float* __restrict__ x,
    const float* __restrict__ Wq, const float* __restrict__ bq,
    const float* __restrict__ Wk, const float* __restrict__ bk,
    const float* __restrict__ Wv, const float* __restrict__ bv)
{
    __shared__ float sW[CC * 80];
    __shared__ float sB[80];
    const int tid = threadIdx.x;
    const int b = blockIdx.y;
    const int s = tid & 63;
    const int h = tid >> 6;
    const int ch0 = h * 20;

    for (int i = tid; i < CC * 80; i += 256) {
        int c = i / 80, j = i % 80;
        float w;
        if (j < 8)       w = Wq[j * CC + c];
        else if (j < 16) w = Wk[(j - 8) * CC + c] * KSCALE;
        else             w = Wv[(j - 16) * CC + c];
        sW[c * 80 + j] = w;
    }
    if (tid < 80) {
        float bb;
        if (tid < 8)       bb = bq[tid];
        else if (tid < 16) bb = bk[tid - 8] * KSCALE;
        else               bb = bv[tid - 16];
        sB[tid] = bb;
    }
    __syncthreads();

    float a[4][20];
#pragma unroll
    for (int p = 0; p < 4; p++)
#pragma unroll
        for (int j = 0; j < 20; j++) a[p][j] = 0.f;

    const int nb = blockIdx.x * 256 + s;
    const float* xb = x + ((size_t)b * CC << 12) + nb;
#pragma unroll 1
    for (int c = 0; c < CC; c += 2) {
        float x0[4], x1[4];
#pragma unroll
        for (int p = 0; p < 4; p++) {
            x0[p] = xb[((size_t)c << 12) + p * 64];
            x1[p] = xb[((size_t)(c + 1) << 12) + p * 64];
        }
        const float* w0 = sW + c * 80 + ch0;
        const float* w1 = sW + (c + 1) * 80 + ch0;
#pragma unroll
        for (int j = 0; j < 20; j++) {
            float ww0 = w0[j], ww1 = w1[j];
#pragma unroll
            for (int p = 0; p < 4; p++) {
                a[p][j] = fmaf(ww0, x0[p], a[p][j]);
                a[p][j] = fmaf(ww1, x1[p], a[p][j]);
            }
        }
    }

#pragma unroll
    for (int p = 0; p < 4; p++) {
        const int n = nb + p * 64;
        if (h == 0) {
            float4 q0 = make_float4(a[p][0] + sB[0], a[p][1] + sB[1],
                                    a[p][2] + sB[2], a[p][3] + sB[3]);
            float4 q1 = make_float4(a[p][4] + sB[4], a[p][5] + sB[5],
                                    a[p][6] + sB[6], a[p][7] + sB[7]);
            float4 k0 = make_float4(a[p][8] + sB[8], a[p][9] + sB[9],
                                    a[p][10] + sB[10], a[p][11] + sB[11]);
            float4 k1 = make_float4(a[p][12] + sB[12], a[p][13] + sB[13],
                                    a[p][14] + sB[14], a[p][15] + sB[15]);
            float4* qo = (float4*)(g_Q + ((b << 12) + n) * DD);
            qo[0] = q0; qo[1] = q1;
            float4* ko = (float4*)(g_K + ((b << 12) + n) * DD);
            ko[0] = k0; ko[1] = k1;
#pragma unroll
            for (int j = 16; j < 20; j++)
                g_Vbf[(((size_t)b * CC + (j - 16)) << 12) + n] =
                    __float2bfloat16(a[p][j] + sB[j]);
        } else {
#pragma unroll
            for (int j = 0; j < 20; j++) {
                int ch = ch0 - 16 + j;
                g_Vbf[(((size_t)b * CC + ch) << 12) + n] =
                    __float2bfloat16(a[p][j] + sB[ch0 + j]);
            }
        }
    }
}

// ---------------- 2: Zp[m] partial column sums via mma ----------------
__global__ void __launch_bounds__(256) zr_kernel()
{
    __shared__ uint32_t sK[64 * 12];
    __shared__ uint32_t sQ[128 * 12];
    __shared__ float    szp[8 * 64];

    const int tid  = threadIdx.x;
    const int lane = tid & 31;
    const int wid  = tid >> 5;
    const int g  = lane >> 2;
    const int tg = lane & 3;
    const int b = blockIdx.z;
    const int ns = blockIdx.y;
    const int m_base = blockIdx.x * 64;

    if (tid < 128) {
        float4 t = ((const float4*)(g_K + ((b << 12) + m_base) * DD))[tid];
        *(uint4*)(sK + (tid >> 1) * 12 + (tid & 1) * 4) = cvt4(t);
    }

    float zacc[16];
#pragma unroll
    for (int i = 0; i < 16; i++) zacc[i] = 0.f;

    for (int t = 0; t < 8; t++) {
        __syncthreads();
        {
            const int nb = ns * 1024 + t * 128;
            float4 tq = ((const float4*)(g_Q + ((b << 12) + nb) * DD))[tid];
            *(uint4*)(sQ + (tid >> 1) * 12 + (tid & 1) * 4) = cvt4(tq);
        }
        __syncthreads();

        const int nrow = wid * 16 + g;
        uint32_t a[4];
        a[0] = sQ[nrow * 12 + tg];
        a[1] = sQ[(nrow + 8) * 12 + tg];
        a[2] = sQ[nrow * 12 + tg + 4];
        a[3] = sQ[(nrow + 8) * 12 + tg + 4];

#pragma unroll
        for (int mt8 = 0; mt8 < 8; mt8++) {
            uint32_t b0 = sK[(mt8 * 8 + g) * 12 + tg];
            uint32_t b1 = sK[(mt8 * 8 + g) * 12 + tg + 4];
            float c[4] = {0.f, 0.f, 0.f, 0.f};
            mma_tf32(c, a, b0, b1);
            zacc[mt8 * 2 + 0] += ex2(c[0]) + ex2(c[2]);
            zacc[mt8 * 2 + 1] += ex2(c[1]) + ex2(c[3]);
        }
    }

#pragma unroll
    for (int i = 0; i < 16; i++) {
        zacc[i] += __shfl_xor_sync(0xffffffffu, zacc[i], 4);
        zacc[i] += __shfl_xor_sync(0xffffffffu, zacc[i], 8);
        zacc[i] += __shfl_xor_sync(0xffffffffu, zacc[i], 16);
    }
    if (lane < 4) {
#pragma unroll
        for (int i = 0; i < 16; i++)
            szp[wid * 64 + (i >> 1) * 8 + lane * 2 + (i & 1)] = zacc[i];
    }
    __syncthreads();
    if (tid < 64) {
        float z = 0.f;
#pragma unroll
        for (int w = 0; w < 8; w++) z += szp[w * 64 + tid];
        g_Zp[(ns * BATCH + b) * NPIX + m_base + tid] = z;
    }
}

// ---------------- 2b: Rz = 1/sum(Zp), plus S partials ----------------
__global__ void __launch_bounds__(256) rza_kernel()
{
    __shared__ float red[256];
    int i = blockIdx.x * 256 + threadIdx.x;
    int b = i >> 12, m = i & 4095;
    float z = g_Zp[(0 * BATCH + b) * NPIX + m]
            + g_Zp[(1 * BATCH + b) * NPIX + m]
            + g_Zp[(2 * BATCH + b) * NPIX + m]
            + g_Zp[(3 * BATCH + b) * NPIX + m];
    float r = 1.0f / z;
    g_Rz[i] = r;
    red[threadIdx.x] = r;
    __syncthreads();
    for (int s = 128; s; s >>= 1) {
        if (threadIdx.x < s) red[threadIdx.x] += red[threadIdx.x + s];
        __syncthreads();
    }
    if (threadIdx.x == 0) g_Sp[blockIdx.x] = red[0];
}

// ---------------- 2c: y[b][c] ----------------
__global__ void __launch_bounds__(256) o0a_kernel(const float* __restrict__ x)
{
    __shared__ float red[256];
    const int c = blockIdx.x, b = blockIdx.y, tid = threadIdx.x;
    const float4* xp = (const float4*)(x + (((size_t)b * CC + c) << 12));
    const float4* rz = (const float4*)(g_Rz + (b << 12));
    float acc = 0.f;
#pragma unroll
    for (int it = 0; it < 4; it++) {
        int m = it * 256 + tid;
        float4 xv = xp[m], rv = rz[m];
        acc = fmaf(xv.x, rv.x, acc);
        acc = fmaf(xv.y, rv.y, acc);
        acc = fmaf(xv.z, rv.z, acc);
        acc = fmaf(xv.w, rv.w, acc);
    }
    red[tid] = acc;
    __syncthreads();
    for (int s = 128; s; s >>= 1) {
        if (tid < s) red[tid] += red[tid + s];
        __syncthreads();
    }
    if (tid == 0) g_y[b * CC + c] = red[0];
}

// ---------------- 2d: O0 ----------------
__global__ void __launch_bounds__(64) o0b_kernel(
    const float* __restrict__ Wv, const float* __restrict__ bv)
{
    __shared__ float sy[64];
    const int b = blockIdx.x, tid = threadIdx.x;
    sy[tid] = g_y[b * CC + tid];
    float S = 0.f;
#pragma unroll
    for (int k = 0; k < 16; k++) S += g_Sp[b * 16 + k];
    __syncthreads();
    float acc = bv[tid] * S;
#pragma unroll 8
    for (int c = 0; c < CC; c++)
        acc = fmaf(Wv[tid * CC + c], sy[c], acc);
    g_O0[b * CC + tid] = acc;
}

// ---------------- 3: term2, ldmatrix/stmatrix fragment path ----------------
#define OFF_PBF 0                       // [128][36] u32, row stride 144 B
#define OFF_VB0 4608                    // [64][36]
#define OFF_VB1 6912
#define OFF_Q   9216                    // [128][12]
#define OFF_K   10752                   // [64][12], row stride 48 B
#define OFF_RZ  11520
#define OUT_SMEM ((11520 + 64) * 4)     // 46336 B

__global__ void __launch_bounds__(256, 2) out_kernel(float* __restrict__ out)
{
    extern __shared__ uint32_t sm[];
    uint32_t* sQ   = sm + OFF_Q;
    uint32_t* sK   = sm + OFF_K;
    float*    sRz  = (float*)(sm + OFF_RZ);

    const int tid  = threadIdx.x;
    const int lane = tid & 31;
    const int wid  = tid >> 5;
    const int b    = blockIdx.y;
    const int n_base = blockIdx.x * 128;
    const int g  = lane >> 2;
    const int tg = lane & 3;

    const int ws    = wid * 16;         // phase-A n rows
    const int Mwoff = (wid & 3) * 32;   // phase-B n offset
    const int Nwoff = (wid >> 2) * 32;  // phase-B c offset

    const uint32_t sb = (uint32_t)__cvta_generic_to_shared(sm);
    const uint32_t pbP = sb + OFF_PBF * 4;
    const uint32_t pbV0 = sb + OFF_VB0 * 4;
    const uint32_t pbK = sb + OFF_K * 4;

    // matrix-op lane addresses
    const uint32_t aStP = pbP + (ws + (lane & 15)) * 144;                       // + mt8*16
    const uint32_t aLdK = pbK + (lane & 7) * 48 + ((lane >> 3) & 1) * 16;       // + mt8*384
    const uint32_t aLdA = pbP + (Mwoff + (lane & 15)) * 144 + ((lane >> 4) & 1) * 16; // + mf*2304 + ks*32
    const uint32_t aLdB0 = (Nwoff + (lane & 7)) * 144 + ((lane >> 3) & 1) * 16; // + Vbase + nf*1152 + ks*32

    // Q tile once
    {
        const float4* qg = (const float4*)(g_Q + ((b << 12) + n_base) * DD);
        float4 t = qg[tid];
        *(uint4*)(sQ + (tid >> 1) * 12 + (tid & 1) * 4) = cvt4(t);
    }
    float4 vK = make_float4(0.f, 0.f, 0.f, 0.f);
    float vRz = 0.f;
    if (tid < 128) vK = ((const float4*)(g_K + (b << 12) * DD))[tid];
    if (tid < 64)  vRz = g_Rz[(b << 12) + tid];
    {   // cp.async V(0) -> buf0
        const char* src = (const char*)(g_Vbf + ((size_t)b * CC << 12));
#pragma unroll
        for (int k = 0; k < 2; k++) {
            int q = tid + k * 256;
            int row = q >> 3, off = (q & 7) * 16;
            cp_async16(pbV0 + row * 144 + off, src + ((size_t)row << 13) + off);
        }
        asm volatile("cp.async.commit_group;");
    }
    __syncthreads();

    uint32_t aq[4];
    aq[0] = sQ[(ws + g) * 12 + tg];
    aq[1] = sQ[(ws + g + 8) * 12 + tg];
    aq[2] = sQ[(ws + g) * 12 + tg + 4];
    aq[3] = sQ[(ws + g + 8) * 12 + tg + 4];

    float acc[32];
#pragma unroll
    for (int i = 0; i < 32; i++) acc[i] = 0.f;

    for (int mt = 0; mt < 64; mt++) {
        const int par = mt & 1;
        __syncthreads();                        // S1: prev phase B done

        // store prefetched K(t)/rz(t)
        if (tid < 128)
            *(uint4*)(sK + (tid >> 1) * 12 + (tid & 1) * 4) = cvt4(vK);
        if (tid < 64) sRz[tid] = vRz;

        // reg-prefetch K(t+1)/rz(t+1)
        if (mt < 63) {
            const int mb2 = (mt + 1) * 64;
            if (tid < 128)
                vK = ((const float4*)(g_K + ((b << 12) + mb2) * DD))[tid];
            if (tid < 64) vRz = g_Rz[(b << 12) + mb2 + tid];
        }
        asm volatile("cp.async.wait_group 0;"); // V(t) arrived
        __syncthreads();                        // S2

        // phase A: QK mma -> delta' -> bf16 via stmatrix
#pragma unroll
        for (int mt8 = 0; mt8 < 8; mt8++) {
            uint32_t kb0, kb1;
            ldsm2(kb0, kb1, aLdK + mt8 * 384);
            float c[4] = {0.f, 0.f, 0.f, 0.f};
            mma_tf32(c, aq, kb0, kb1);
            float2 rr = *(const float2*)(sRz + mt8 * 8 + tg * 2);
            float d0 = fmaf(ex2(c[0]), rr.x, -rr.x);
            float d1 = fmaf(ex2(c[1]), rr.y, -rr.y);
            float d2 = fmaf(ex2(c[2]), rr.x, -rr.x);
            float d3 = fmaf(ex2(c[3]), rr.y, -rr.y);
            stsm2(aStP + mt8 * 16, bf2(d0, d1), bf2(d2, d3));
        }

        // cp.async V(t+1) into other buffer
        if (mt < 63) {
            const char* src = (const char*)(g_Vbf + ((size_t)b * CC << 12))
                            + (mt + 1) * 128;
            uint32_t dbase = sb + (par ? OFF_VB0 : OFF_VB1) * 4;
#pragma unroll
            for (int k = 0; k < 2; k++) {
                int q = tid + k * 256;
                int row = q >> 3, off = (q & 7) * 16;
                cp_async16(dbase + row * 144 + off,
                           src + ((size_t)row << 13) + off);
            }
            asm volatile("cp.async.commit_group;");
        }
        __syncthreads();                        // S3: P(t) visible

        // phase B: warp covers n 32 x c 32 x m 64, all ldmatrix
        const uint32_t vbase = sb + (par ? OFF_VB1 : OFF_VB0) * 4 + aLdB0;
#pragma unroll
        for (int ks = 0; ks < 4; ks++) {
            uint32_t a0[4], a1[4];
            ldsm4(a0, aLdA + ks * 32);
            ldsm4(a1, aLdA + 2304 + ks * 32);
#pragma unroll
            for (int nf = 0; nf < 4; nf++) {
                uint32_t b0, b1;
                ldsm2(b0, b1, vbase + nf * 1152 + ks * 32);
                mma_bf16(acc + (0 * 4 + nf) * 4, a0, b0, b1);
                mma_bf16(acc + (1 * 4 + nf) * 4, a1, b0, b1);
            }
        }
    }

    // epilogue: direct store + O0
#pragma unroll
    for (int mf = 0; mf < 2; mf++)
#pragma unroll
        for (int nf = 0; nf < 4; nf++) {
            int n = n_base + Mwoff + mf * 16 + g;
            int c = Nwoff + nf * 8 + tg * 2;
            float o0a_ = __ldg(g_O0 + b * CC + c);
            float o0b_ = __ldg(g_O0 + b * CC + c + 1);
            float* o = out + (((size_t)b * CC + c) << 12) + n;
            const float* ac = acc + (mf * 4 + nf) * 4;
            o[0]        = ac[0] + o0a_;
            o[4096]     = ac[1] + o0b_;
            o[8]        = ac[2] + o0a_;
            o[4096 + 8] = ac[3] + o0b_;
        }
}

// ---------------- launch ----------------
extern "C" void kernel_launch(void* const* d_in, const int* in_sizes, int n_in,
                              void* d_out, int out_size)
{
    const float* x  = (const float*)d_in[0];
    const float* Wq = (const float*)d_in[1];
    const float* bq = (const float*)d_in[2];
    const float* Wk = (const float*)d_in[3];
    const float* bk = (const float*)d_in[4];
    const float* Wv = (const float*)d_in[5];
    const float* bv = (const float*)d_in[6];
    float* out = (float*)d_out;

    cudaFuncSetAttribute(out_kernel, cudaFuncAttributeMaxDynamicSharedMemorySize, OUT_SMEM);

    proj_kernel<<<dim3(16, BATCH), 256>>>(x, Wq, bq, Wk, bk, Wv, bv);
    zr_kernel<<<dim3(64, 4, BATCH), 256>>>();
    rza_kernel<<<128, 256>>>();
    o0a_kernel<<<dim3(CC, BATCH), 256>>>(x);
    o0b_kernel<<<BATCH, 64>>>(Wv, bv);
    out_kernel<<<dim3(32, BATCH), 256, OUT_SMEM>>>(out);
}